// round 16
// baseline (speedup 1.0000x reference)
#include <cuda_runtime.h>
#include <cuda_fp16.h>
#include <math.h>
#include <stdint.h>

#define BB 4
#define NN 2048
#define DD 512
#define HH 8
#define DH 64
#define HD 512        // HH*DH
#define QKVC 1536     // 3*HH*DH
#define MAXREL 200
#define LOG2E 1.44269504088896f

// ---- scratch (static device globals; no allocation allowed) ----
__device__ __half g_xnh[BB * NN * DD];       // LN output, fp16
__device__ __half g_wqkvTh[QKVC * DD];       // fp16 weights, [n][k]
__device__ __half g_woutTh[DD * HD];         // fp16 weights, [n][k]
__device__ __half g_qh[BB * HH * NN * DH];   // [b,h,n,d]  fp16, pre-scaled by 0.125*log2e
__device__ __half g_kh[BB * HH * NN * DH];   // [b,h,n,d]  fp16
__device__ __half g_vTh[BB * HH * DH * NN];  // [b,h,d,n]  fp16
__device__ __half g_attnh[BB * NN * HD];     // fp16
__device__ __half g_biasH[NN * NN];          // (rel bias)*log2e, masked -> -60000

__device__ __forceinline__ void cp16(uint32_t s, const void* g) {
    asm volatile("cp.async.ca.shared.global [%0], [%1], 16;" :: "r"(s), "l"(g));
}
#define CP_COMMIT()  asm volatile("cp.async.commit_group;")
#define CP_WAIT(N)   asm volatile("cp.async.wait_group %0;" :: "n"(N))

#define MMA_F16(d, a0,a1,a2,a3, b0,b1)                                         \
    asm volatile("mma.sync.aligned.m16n8k16.row.col.f32.f16.f16.f32 "          \
        "{%0,%1,%2,%3},{%4,%5,%6,%7},{%8,%9},{%0,%1,%2,%3};"                   \
        : "+f"((d)[0]), "+f"((d)[1]), "+f"((d)[2]), "+f"((d)[3])               \
        : "r"(a0), "r"(a1), "r"(a2), "r"(a3), "r"(b0), "r"(b1))

// ldmatrix x4: 4 consecutive 8x8 b16 units
__device__ __forceinline__ void ldsm4(uint32_t& r0, uint32_t& r1, uint32_t& r2, uint32_t& r3,
                                      uint32_t a) {
    asm volatile("ldmatrix.sync.aligned.m8n8.x4.shared.b16 {%0,%1,%2,%3}, [%4];"
        : "=r"(r0), "=r"(r1), "=r"(r2), "=r"(r3) : "r"(a));
}

// ================= merged prep: weight transposes + bias table + layernorm =================
// blocks [0,768)      : Wqkv transpose  (K=DD, N=QKVC)  -> g_wqkvTh [n][k]
// blocks [768,1024)   : Wout transpose  (K=HD, N=DD)    -> g_woutTh [n][k]
// blocks [1024,5120)  : bias table
// blocks [5120,6144)  : layernorm (8 rows per block, warp per row)
__global__ __launch_bounds__(256) void prep_kernel(const float* __restrict__ x,
                                                   const float* __restrict__ gamma,
                                                   const float* __restrict__ beta,
                                                   const float* __restrict__ Wqkv,
                                                   const float* __restrict__ Wout,
                                                   const float* __restrict__ rel_table,
                                                   const int* __restrict__ tmask) {
    int blk = blockIdx.x;
    if (blk < 1024) {
        // ---- weight transpose ----
        const float* W; __half* WT; int K, N, n0, k0;
        if (blk < 768) {
            W = Wqkv; WT = g_wqkvTh; K = DD; N = QKVC;
            n0 = (blk % 48) * 32; k0 = (blk / 48) * 32;
        } else {
            int j = blk - 768;
            W = Wout; WT = g_woutTh; K = HD; N = DD;
            n0 = (j % 16) * 32; k0 = (j / 16) * 32;
        }
        __shared__ float t[32][33];
        int tx = threadIdx.x & 31, ty = threadIdx.x >> 5;
#pragma unroll
        for (int i = 0; i < 4; ++i)
            t[ty + i * 8][tx] = W[(size_t)(k0 + ty + i * 8) * N + n0 + tx];
        __syncthreads();
#pragma unroll
        for (int i = 0; i < 4; ++i)
            WT[(size_t)(n0 + ty + i * 8) * K + k0 + tx] = __float2half_rn(t[tx][ty + i * 8]);
    } else if (blk < 5120) {
        // ---- bias table ----
        int i = (blk - 1024) * 256 + threadIdx.x;    // 4-element index over NN*NN/4
        int r = i >> 9;
        int c0 = (i << 2) & (NN - 1);
        int4 m = ((const int4*)tmask)[i];
        float o[4];
#pragma unroll
        for (int j = 0; j < 4; ++j) {
            int rel = min(max(r - c0 - j, -(MAXREL - 1)), MAXREL - 1) + (MAXREL - 1);
            float v = __ldg(&rel_table[rel]) * LOG2E;
            int mm = (j == 0) ? m.x : (j == 1) ? m.y : (j == 2) ? m.z : m.w;
            o[j] = (mm == 0) ? -60000.0f : v;
        }
        ((__half2*)g_biasH)[i * 2]     = __floats2half2_rn(o[0], o[1]);
        ((__half2*)g_biasH)[i * 2 + 1] = __floats2half2_rn(o[2], o[3]);
    } else {
        // ---- layernorm ----
        int warp = ((blk - 5120) * 256 + threadIdx.x) >> 5;
        int lane = threadIdx.x & 31;
        if (warp >= BB * NN) return;
        const float4* row = reinterpret_cast<const float4*>(x + (size_t)warp * DD);
        float4 v[4];
        float s = 0.f, ss = 0.f;
#pragma unroll
        for (int i = 0; i < 4; ++i) {
            v[i] = row[lane + i * 32];
            s  += v[i].x + v[i].y + v[i].z + v[i].w;
            ss += v[i].x * v[i].x + v[i].y * v[i].y + v[i].z * v[i].z + v[i].w * v[i].w;
        }
#pragma unroll
        for (int off = 16; off; off >>= 1) {
            s  += __shfl_xor_sync(0xffffffffu, s,  off);
            ss += __shfl_xor_sync(0xffffffffu, ss, off);
        }
        float mu = s * (1.0f / DD);
        float rs = rsqrtf(ss * (1.0f / DD) - mu * mu + 1e-5f);
        __half2* dst = reinterpret_cast<__half2*>(g_xnh + (size_t)warp * DD);
#pragma unroll
        for (int i = 0; i < 4; ++i) {
            int c = lane + i * 32;
            float4 gm = ((const float4*)gamma)[c];
            float4 be = ((const float4*)beta)[c];
            dst[c * 2]     = __floats2half2_rn((v[i].x - mu) * rs * gm.x + be.x,
                                               (v[i].y - mu) * rs * gm.y + be.y);
            dst[c * 2 + 1] = __floats2half2_rn((v[i].z - mu) * rs * gm.z + be.z,
                                               (v[i].w - mu) * rs * gm.w + be.w);
        }
    }
}

// ========== fp16 GEMM: 128x128x32 tile, 8 warps (4m x 2n), ldmatrix fragments ==========
// smem halves: As[2][128][40] @0 (buf stride 5120), Bs[2][128][40] @10240 (rows = n)
#define GAH(buf, r, c)  ((buf) * 5120 + (r) * 40 + (c))
#define GBH(buf, r, c)  (10240 + (buf) * 5120 + (r) * 40 + (c))

#define GEMM_LOADA(buf, Ap, lda, k0)                                           \
    {                                                                          \
        _Pragma("unroll")                                                      \
        for (int i = 0; i < 2; ++i) {                                          \
            int idx = tid + i * 256;                                           \
            int r = idx >> 2, c = (idx & 3) * 8;                               \
            cp16(smb + GAH(buf, r, c) * 2, (Ap) + (size_t)(m0 + r) * (lda) + (k0) + c); \
        }                                                                      \
    }
#define GEMM_LOADB(buf, BTp, ldk, k0)                                          \
    {                                                                          \
        _Pragma("unroll")                                                      \
        for (int i = 0; i < 2; ++i) {                                          \
            int idx = tid + i * 256;                                           \
            int r = idx >> 2, c = (idx & 3) * 8;                               \
            cp16(smb + GBH(buf, r, c) * 2, (BTp) + (size_t)(n0 + r) * (ldk) + (k0) + c); \
        }                                                                      \
    }

#define GEMM_MAIN(Ap, lda, BTp, ldk, KDIM)                                     \
    float acc[2][8][4] = {};                                                   \
    GEMM_LOADA(0, Ap, lda, 0);                                                 \
    GEMM_LOADB(0, BTp, ldk, 0);                                                \
    CP_COMMIT();                                                               \
    for (int k0 = 0; k0 < (KDIM); k0 += 32) {                                  \
        int buf = (k0 >> 5) & 1;                                               \
        if (k0 > 0) __syncthreads();                                           \
        if (k0 + 32 < (KDIM)) {                                                \
            GEMM_LOADA(buf ^ 1, Ap, lda, k0 + 32);                             \
            GEMM_LOADB(buf ^ 1, BTp, ldk, k0 + 32);                            \
            CP_COMMIT();                                                       \
            CP_WAIT(1);                                                        \
        } else {                                                               \
            CP_WAIT(0);                                                        \
        }                                                                      \
        __syncthreads();                                                       \
        _Pragma("unroll")                                                      \
        for (int ks = 0; ks < 2; ++ks) {                                       \
            uint32_t af[2][4];                                                 \
            _Pragma("unroll")                                                  \
            for (int mi = 0; mi < 2; ++mi)                                     \
                ldsm4(af[mi][0], af[mi][1], af[mi][2], af[mi][3],              \
                      smb + (uint32_t)GAH(buf, wm + mi * 16 + fr, ks * 16 + fc8) * 2); \
            _Pragma("unroll")                                                  \
            for (int nj = 0; nj < 4; ++nj) {                                   \
                uint32_t b0, b1, b2, b3;                                       \
                ldsm4(b0, b1, b2, b3,                                          \
                      smb + (uint32_t)GBH(buf, wn + nj * 16 + fr, ks * 16 + fc8) * 2); \
                MMA_F16(acc[0][2 * nj],     af[0][0], af[0][1], af[0][2], af[0][3], b0, b2); \
                MMA_F16(acc[0][2 * nj + 1], af[0][0], af[0][1], af[0][2], af[0][3], b1, b3); \
                MMA_F16(acc[1][2 * nj],     af[1][0], af[1][1], af[1][2], af[1][3], b0, b2); \
                MMA_F16(acc[1][2 * nj + 1], af[1][0], af[1][1], af[1][2], af[1][3], b1, b3); \
            }                                                                  \
        }                                                                      \
    }

// ================= QKV GEMM (fp16 MMA): xnh[8192,512] x WqkvTh =================
__global__ __launch_bounds__(256, 2) void qkv_mma_kernel() {
    __shared__ __half sm[20480];
    uint32_t smb = (uint32_t)__cvta_generic_to_shared(sm);
    int tid = threadIdx.x;
    int lane = tid & 31, wid = tid >> 5;
    int g = lane >> 2, tig = lane & 3;
    int fr = lane & 15, fc8 = (lane >> 4) * 8;
    int wm = (wid >> 1) * 32, wn = (wid & 1) * 64;
    int m0 = blockIdx.y * 128, n0 = blockIdx.x * 128;

    GEMM_MAIN(g_xnh, DD, g_wqkvTh, DD, DD);

    const float QSCALE = 0.125f * LOG2E;
#pragma unroll
    for (int ni = 0; ni < 8; ++ni) {
        int c = n0 + wn + ni * 8 + 2 * tig;
        int part = c >> 9, w = c & 511;
        int h = w >> 6, dd = w & 63;
#pragma unroll
        for (int mi = 0; mi < 2; ++mi) {
#pragma unroll
            for (int half = 0; half < 2; ++half) {
                int r = m0 + wm + mi * 16 + g + half * 8;
                int b = r >> 11, n = r & (NN - 1);
                size_t bh = (size_t)(b * HH + h);
                float v0 = acc[mi][ni][half * 2 + 0];
                float v1 = acc[mi][ni][half * 2 + 1];
                if (part == 0) {
                    *(__half2*)&g_qh[(bh * NN + n) * DH + dd] =
                        __floats2half2_rn(v0 * QSCALE, v1 * QSCALE);
                } else if (part == 1) {
                    *(__half2*)&g_kh[(bh * NN + n) * DH + dd] =
                        __floats2half2_rn(v0, v1);
                } else {
                    g_vTh[(bh * DH + dd) * NN + n]     = __float2half_rn(v0);
                    g_vTh[(bh * DH + dd + 1) * NN + n] = __float2half_rn(v1);
                }
            }
        }
    }
}

// ================= Out GEMM (fp16 MMA): attnh[8192,512] x WoutTh + bias =================
__global__ __launch_bounds__(256, 2) void out_mma_kernel(const float* __restrict__ bout,
                                                         float* __restrict__ out) {
    __shared__ __half sm[20480];
    uint32_t smb = (uint32_t)__cvta_generic_to_shared(sm);
    int tid = threadIdx.x;
    int lane = tid & 31, wid = tid >> 5;
    int g = lane >> 2, tig = lane & 3;
    int fr = lane & 15, fc8 = (lane >> 4) * 8;
    int wm = (wid >> 1) * 32, wn = (wid & 1) * 64;
    int m0 = blockIdx.y * 128, n0 = blockIdx.x * 128;

    GEMM_MAIN(g_attnh, HD, g_woutTh, HD, HD);

#pragma unroll
    for (int ni = 0; ni < 8; ++ni) {
        int c = n0 + wn + ni * 8 + 2 * tig;
        float2 bo = *(const float2*)&bout[c];
#pragma unroll
        for (int mi = 0; mi < 2; ++mi) {
#pragma unroll
            for (int half = 0; half < 2; ++half) {
                int r = m0 + wm + mi * 16 + g + half * 8;
                *(float2*)&out[(size_t)r * DD + c] =
                    make_float2(acc[mi][ni][half * 2 + 0] + bo.x,
                                acc[mi][ni][half * 2 + 1] + bo.y);
            }
        }
    }
}

// ================= Flash attention: 128-key stages, Q frags hoisted =================
// smem halves: QS[128][72] @0, KS[2][128][72] @9216 (buf 9216), VS[2][64][136] @27648 (buf 8704)
#define HQS   0
#define HKS   9216
#define HKSTG 9216
#define HVS   27648
#define HVSTG 8704
#define FLASH_SMEM (45056 * 2)
#define NSTG (NN / 128)

__global__ __launch_bounds__(256, 2) void flash_mma_kernel() {
    extern __shared__ __half smh[];
    uint32_t smb = (uint32_t)__cvta_generic_to_shared(smh);

    int tid  = threadIdx.x;
    int lane = tid & 31, wid = tid >> 5;
    int tig = lane & 3;
    int bh = blockIdx.y;
    int q0 = blockIdx.x * 128;
    const __half* Q  = g_qh  + (size_t)bh * NN * DH;
    const __half* K  = g_kh  + (size_t)bh * NN * DH;
    const __half* Vt = g_vTh + (size_t)bh * DH * NN;

    int hr = tid >> 3;            // 0..31
    int hc = (tid & 7) * 8;       // 0..56  (64-wide rows)
    int vr = tid >> 4;            // 0..15
    int vc = (tid & 15) * 8;      // 0..120 (128-wide rows)

    // ---- issue Q (128x64) + stage0 K (128x64) + stage0 V (64x128) ----
#pragma unroll
    for (int i = 0; i < 4; ++i) {
        int r = hr + i * 32;
        cp16(smb + (HQS + r * 72 + hc) * 2, Q + (size_t)(q0 + r) * DH + hc);
        cp16(smb + (HKS + r * 72 + hc) * 2, K + (size_t)r * DH + hc);
    }
#pragma unroll
    for (int i = 0; i < 4; ++i) {
        int d = vr + i * 16;
        cp16(smb + (HVS + d * 136 + vc) * 2, Vt + (size_t)d * NN + vc);
    }
    CP_COMMIT();

    float oa[8][4] = {};
    float mi[2] = {-INFINITY, -INFINITY};
    float li[2] = {0.f, 0.f};
    const uint32_t ONES = 0x3C003C00u;

    const int g   = lane >> 2;
    const int m_row = wid * 16 + g;
    const int fr  = lane & 15;
    const int fc8 = (lane >> 4) * 8;

    CP_WAIT(0);
    __syncthreads();

    // ---- hoist Q fragments (loop-invariant) ----
    uint32_t qf[4][4];
    {
        uint32_t qa = smb + ((uint32_t)(HQS + (wid * 16 + fr) * 72 + fc8) << 1);
#pragma unroll
        for (int kc = 0; kc < 4; ++kc) {
            ldsm4(qf[kc][0], qf[kc][1], qf[kc][2], qf[kc][3], qa);
            qa += 32;
        }
    }

    for (int t = 0; t < NSTG; ++t) {
        int cur = t & 1;
        int k0 = t * 128;

        if (t > 0) __syncthreads();        // all warps done with buffer we overwrite
        if (t + 1 < NSTG) {
            int nxt = cur ^ 1;
#pragma unroll
            for (int i = 0; i < 4; ++i) {
                int r = hr + i * 32;
                cp16(smb + (HKS + nxt * HKSTG + r * 72 + hc) * 2,
                     K + (size_t)(k0 + 128 + r) * DH + hc);
            }
#pragma unroll
            for (int i = 0; i < 4; ++i) {
                int d = vr + i * 16;
                cp16(smb + (HVS + nxt * HVSTG + d * 136 + vc) * 2,
                     Vt + (size_t)d * NN + k0 + 128 + vc);
            }
            CP_COMMIT();
            CP_WAIT(1);
        } else {
            CP_WAIT(0);
        }
        __syncthreads();                   // stage t visible

        uint32_t kbase = smb + ((uint32_t)(HKS + cur * HKSTG) << 1);
        uint32_t vbase = smb + ((uint32_t)(HVS + cur * HVSTG) << 1);

        // ---- two 64-key chunks, no barrier between ----
#pragma unroll
        for (int c = 0; c < 2; ++c) {
            // bias for this chunk
            __half2 bb[2][8];
            {
                const __half2* bp0 = (const __half2*)(g_biasH + (size_t)(q0 + m_row) * NN
                                                      + k0 + c * 64) + tig;
                const __half2* bp1 = (const __half2*)(g_biasH + (size_t)(q0 + m_row + 8) * NN
                                                      + k0 + c * 64) + tig;
#pragma unroll
                for (int nt = 0; nt < 8; ++nt) {
                    bb[0][nt] = bp0[nt * 4];
                    bb[1][nt] = bp1[nt * 4];
                }
            }

            uint32_t ka[4], va[4];
#pragma unroll
            for (int j = 0; j < 4; ++j) {
                ka[j] = kbase + ((uint32_t)((c * 64 + j * 16 + fr) * 72 + fc8) << 1);
                va[j] = vbase + ((uint32_t)((j * 16 + fr) * 136 + c * 64 + fc8) << 1);
            }

            // S accumulators init with bias
            float sa[8][4];
#pragma unroll
            for (int nt = 0; nt < 8; ++nt) {
                float2 b0 = __half22float2(bb[0][nt]);
                float2 b1 = __half22float2(bb[1][nt]);
                sa[nt][0] = b0.x; sa[nt][1] = b0.y;
                sa[nt][2] = b1.x; sa[nt][3] = b1.y;
            }

            // S = bias + Q K^T
#pragma unroll
            for (int kc = 0; kc < 4; ++kc) {
#pragma unroll
                for (int kt = 0; kt < 4; ++kt) {
                    uint32_t b0, b1, b2, b3;
                    ldsm4(b0, b1, b2, b3, ka[kt]);  ka[kt] += 32;
                    MMA_F16(sa[2 * kt],     qf[kc][0], qf[kc][1], qf[kc][2], qf[kc][3], b0, b2);
                    MMA_F16(sa[2 * kt + 1], qf[kc][0], qf[kc][1], qf[kc][2], qf[kc][3], b1, b3);
                }
            }

            // online softmax -> packed P fragments
            uint32_t ph[2][8];
            float fr2[2];
#pragma unroll
            for (int ri = 0; ri < 2; ++ri) {
                float mx = -INFINITY;
#pragma unroll
                for (int nt = 0; nt < 8; ++nt)
                    mx = fmaxf(mx, fmaxf(sa[nt][ri * 2 + 0], sa[nt][ri * 2 + 1]));
                mx = fmaxf(mx, __shfl_xor_sync(0xffffffffu, mx, 1));
                mx = fmaxf(mx, __shfl_xor_sync(0xffffffffu, mx, 2));
                float mnew = fmaxf(mi[ri], mx);
                fr2[ri] = exp2f(mi[ri] - mnew);
#pragma unroll
                for (int nt = 0; nt < 8; ++nt) {
                    __half2 tt = __floats2half2_rn(sa[nt][ri * 2 + 0] - mnew,
                                                   sa[nt][ri * 2 + 1] - mnew);
                    __half2 e = h2exp2(tt);
                    ph[ri][nt] = *(uint32_t*)&e;
                }
                mi[ri] = mnew;
#pragma unroll
                for (int nt = 0; nt < 8; ++nt) {
                    oa[nt][ri * 2 + 0] *= fr2[ri];
                    oa[nt][ri * 2 + 1] *= fr2[ri];
                }
            }

            // O += P V, row sums via ones-MMA
            float ls[4] = {};
#pragma unroll
            for (int kc = 0; kc < 4; ++kc) {
                uint32_t a0 = ph[0][2 * kc];
                uint32_t a1 = ph[1][2 * kc];
                uint32_t a2 = ph[0][2 * kc + 1];
                uint32_t a3 = ph[1][2 * kc + 1];
                MMA_F16(ls, a0, a1, a2, a3, ONES, ONES);
#pragma unroll
                for (int dt = 0; dt < 4; ++dt) {
                    uint32_t b0, b1, b2, b3;
                    ldsm4(b0, b1, b2, b3, va[dt]);  va[dt] += 32;
                    MMA_F16(oa[2 * dt],     a0, a1, a2, a3, b0, b2);
                    MMA_F16(oa[2 * dt + 1], a0, a1, a2, a3, b1, b3);
                }
            }
            li[0] = li[0] * fr2[0] + ls[0];
            li[1] = li[1] * fr2[1] + ls[2];
        }
    }

    // ---- finalize: fp16 attn [B, N, H*d] ----
    int b = bh >> 3, h = bh & 7;
    float inv0 = 1.0f / li[0], inv1 = 1.0f / li[1];
#pragma unroll
    for (int nt = 0; nt < 8; ++nt) {
        int col = h * DH + nt * 8 + 2 * tig;
        int r0 = q0 + m_row;
        *(__half2*)&g_attnh[((size_t)(b * NN + r0)) * HD + col] =
            __floats2half2_rn(oa[nt][0] * inv0, oa[nt][1] * inv0);
        *(__half2*)&g_attnh[((size_t)(b * NN + r0 + 8)) * HD + col] =
            __floats2half2_rn(oa[nt][2] * inv1, oa[nt][3] * inv1);
    }
}

extern "C" void kernel_launch(void* const* d_in, const int* in_sizes, int n_in,
                              void* d_out, int out_size) {
    const float* x     = (const float*)d_in[0];
    const float* gamma = (const float*)d_in[1];
    const float* beta  = (const float*)d_in[2];
    const float* Wqkv  = (const float*)d_in[3];
    const float* Wout  = (const float*)d_in[4];
    const float* bout  = (const float*)d_in[5];
    const float* rel   = (const float*)d_in[6];
    const int*   tmask = (const int*)d_in[7];
    float* out = (float*)d_out;

    prep_kernel<<<6144, 256>>>(x, gamma, beta, Wqkv, Wout, rel, tmask);
    qkv_mma_kernel<<<dim3(QKVC / 128, (BB * NN) / 128), 256>>>();

    cudaFuncSetAttribute(flash_mma_kernel, cudaFuncAttributeMaxDynamicSharedMemorySize, FLASH_SMEM);
    flash_mma_kernel<<<dim3(NN / 128, BB * HH), 256, FLASH_SMEM>>>();

    out_mma_kernel<<<dim3(DD / 128, (BB * NN) / 128), 256>>>(bout, out);
}

// round 17
// speedup vs baseline: 1.0560x; 1.0560x over previous
#include <cuda_runtime.h>
#include <cuda_fp16.h>
#include <math.h>
#include <stdint.h>

#define BB 4
#define NN 2048
#define DD 512
#define HH 8
#define DH 64
#define HD 512        // HH*DH
#define QKVC 1536     // 3*HH*DH
#define MAXREL 200
#define LOG2E 1.44269504088896f

// ---- scratch (static device globals; no allocation allowed) ----
__device__ __half g_xnh[BB * NN * DD];       // LN output, fp16
__device__ __half g_wqkvTh[QKVC * DD];       // fp16 weights, [n][k]
__device__ __half g_woutTh[DD * HD];         // fp16 weights, [n][k]
__device__ __half g_qh[BB * HH * NN * DH];   // [b,h,n,d]  fp16, pre-scaled by 0.125*log2e
__device__ __half g_kh[BB * HH * NN * DH];   // [b,h,n,d]  fp16
__device__ __half g_vTh[BB * HH * DH * NN];  // [b,h,d,n]  fp16
__device__ __half g_attnh[BB * NN * HD];     // fp16
__device__ __half g_biasH[NN * NN];          // (rel bias)*log2e, masked -> -60000

__device__ __forceinline__ void cp16(uint32_t s, const void* g) {
    asm volatile("cp.async.ca.shared.global [%0], [%1], 16;" :: "r"(s), "l"(g));
}
#define CP_COMMIT()  asm volatile("cp.async.commit_group;")
#define CP_WAIT(N)   asm volatile("cp.async.wait_group %0;" :: "n"(N))

#define MMA_F16(d, a0,a1,a2,a3, b0,b1)                                         \
    asm volatile("mma.sync.aligned.m16n8k16.row.col.f32.f16.f16.f32 "          \
        "{%0,%1,%2,%3},{%4,%5,%6,%7},{%8,%9},{%0,%1,%2,%3};"                   \
        : "+f"((d)[0]), "+f"((d)[1]), "+f"((d)[2]), "+f"((d)[3])               \
        : "r"(a0), "r"(a1), "r"(a2), "r"(a3), "r"(b0), "r"(b1))

// ldmatrix x4: 4 consecutive 8x8 b16 units
__device__ __forceinline__ void ldsm4(uint32_t& r0, uint32_t& r1, uint32_t& r2, uint32_t& r3,
                                      uint32_t a) {
    asm volatile("ldmatrix.sync.aligned.m8n8.x4.shared.b16 {%0,%1,%2,%3}, [%4];"
        : "=r"(r0), "=r"(r1), "=r"(r2), "=r"(r3) : "r"(a));
}

// ================= merged prep: weight transposes + bias table + layernorm =================
// blocks [0,768)      : Wqkv transpose  (K=DD, N=QKVC)  -> g_wqkvTh [n][k]
// blocks [768,1024)   : Wout transpose  (K=HD, N=DD)    -> g_woutTh [n][k]
// blocks [1024,5120)  : bias table
// blocks [5120,6144)  : layernorm (8 rows per block, warp per row)
__global__ __launch_bounds__(256) void prep_kernel(const float* __restrict__ x,
                                                   const float* __restrict__ gamma,
                                                   const float* __restrict__ beta,
                                                   const float* __restrict__ Wqkv,
                                                   const float* __restrict__ Wout,
                                                   const float* __restrict__ rel_table,
                                                   const int* __restrict__ tmask) {
    int blk = blockIdx.x;
    if (blk < 1024) {
        const float* W; __half* WT; int K, N, n0, k0;
        if (blk < 768) {
            W = Wqkv; WT = g_wqkvTh; K = DD; N = QKVC;
            n0 = (blk % 48) * 32; k0 = (blk / 48) * 32;
        } else {
            int j = blk - 768;
            W = Wout; WT = g_woutTh; K = HD; N = DD;
            n0 = (j % 16) * 32; k0 = (j / 16) * 32;
        }
        __shared__ float t[32][33];
        int tx = threadIdx.x & 31, ty = threadIdx.x >> 5;
#pragma unroll
        for (int i = 0; i < 4; ++i)
            t[ty + i * 8][tx] = W[(size_t)(k0 + ty + i * 8) * N + n0 + tx];
        __syncthreads();
#pragma unroll
        for (int i = 0; i < 4; ++i)
            WT[(size_t)(n0 + ty + i * 8) * K + k0 + tx] = __float2half_rn(t[tx][ty + i * 8]);
    } else if (blk < 5120) {
        int i = (blk - 1024) * 256 + threadIdx.x;    // 4-element index over NN*NN/4
        int r = i >> 9;
        int c0 = (i << 2) & (NN - 1);
        int4 m = ((const int4*)tmask)[i];
        float o[4];
#pragma unroll
        for (int j = 0; j < 4; ++j) {
            int rel = min(max(r - c0 - j, -(MAXREL - 1)), MAXREL - 1) + (MAXREL - 1);
            float v = __ldg(&rel_table[rel]) * LOG2E;
            int mm = (j == 0) ? m.x : (j == 1) ? m.y : (j == 2) ? m.z : m.w;
            o[j] = (mm == 0) ? -60000.0f : v;
        }
        ((__half2*)g_biasH)[i * 2]     = __floats2half2_rn(o[0], o[1]);
        ((__half2*)g_biasH)[i * 2 + 1] = __floats2half2_rn(o[2], o[3]);
    } else {
        int warp = ((blk - 5120) * 256 + threadIdx.x) >> 5;
        int lane = threadIdx.x & 31;
        if (warp >= BB * NN) return;
        const float4* row = reinterpret_cast<const float4*>(x + (size_t)warp * DD);
        float4 v[4];
        float s = 0.f, ss = 0.f;
#pragma unroll
        for (int i = 0; i < 4; ++i) {
            v[i] = row[lane + i * 32];
            s  += v[i].x + v[i].y + v[i].z + v[i].w;
            ss += v[i].x * v[i].x + v[i].y * v[i].y + v[i].z * v[i].z + v[i].w * v[i].w;
        }
#pragma unroll
        for (int off = 16; off; off >>= 1) {
            s  += __shfl_xor_sync(0xffffffffu, s,  off);
            ss += __shfl_xor_sync(0xffffffffu, ss, off);
        }
        float mu = s * (1.0f / DD);
        float rs = rsqrtf(ss * (1.0f / DD) - mu * mu + 1e-5f);
        __half2* dst = reinterpret_cast<__half2*>(g_xnh + (size_t)warp * DD);
#pragma unroll
        for (int i = 0; i < 4; ++i) {
            int c = lane + i * 32;
            float4 gm = ((const float4*)gamma)[c];
            float4 be = ((const float4*)beta)[c];
            dst[c * 2]     = __floats2half2_rn((v[i].x - mu) * rs * gm.x + be.x,
                                               (v[i].y - mu) * rs * gm.y + be.y);
            dst[c * 2 + 1] = __floats2half2_rn((v[i].z - mu) * rs * gm.z + be.z,
                                               (v[i].w - mu) * rs * gm.w + be.w);
        }
    }
}

// ========== fp16 GEMM: 128x128x32 tile, 8 warps (4m x 2n), ldmatrix fragments ==========
// smem halves: As[2][128][40] @0 (buf stride 5120), Bs[2][128][40] @10240 (rows = n)
#define GAH(buf, r, c)  ((buf) * 5120 + (r) * 40 + (c))
#define GBH(buf, r, c)  (10240 + (buf) * 5120 + (r) * 40 + (c))

#define GEMM_LOADA(buf, Ap, lda, k0)                                           \
    {                                                                          \
        _Pragma("unroll")                                                      \
        for (int i = 0; i < 2; ++i) {                                          \
            int idx = tid + i * 256;                                           \
            int r = idx >> 2, c = (idx & 3) * 8;                               \
            cp16(smb + GAH(buf, r, c) * 2, (Ap) + (size_t)(m0 + r) * (lda) + (k0) + c); \
        }                                                                      \
    }
#define GEMM_LOADB(buf, BTp, ldk, k0)                                          \
    {                                                                          \
        _Pragma("unroll")                                                      \
        for (int i = 0; i < 2; ++i) {                                          \
            int idx = tid + i * 256;                                           \
            int r = idx >> 2, c = (idx & 3) * 8;                               \
            cp16(smb + GBH(buf, r, c) * 2, (BTp) + (size_t)(n0 + r) * (ldk) + (k0) + c); \
        }                                                                      \
    }

#define GEMM_MAIN(Ap, lda, BTp, ldk, KDIM)                                     \
    float acc[2][8][4] = {};                                                   \
    GEMM_LOADA(0, Ap, lda, 0);                                                 \
    GEMM_LOADB(0, BTp, ldk, 0);                                                \
    CP_COMMIT();                                                               \
    for (int k0 = 0; k0 < (KDIM); k0 += 32) {                                  \
        int buf = (k0 >> 5) & 1;                                               \
        if (k0 > 0) __syncthreads();                                           \
        if (k0 + 32 < (KDIM)) {                                                \
            GEMM_LOADA(buf ^ 1, Ap, lda, k0 + 32);                             \
            GEMM_LOADB(buf ^ 1, BTp, ldk, k0 + 32);                            \
            CP_COMMIT();                                                       \
            CP_WAIT(1);                                                        \
        } else {                                                               \
            CP_WAIT(0);                                                        \
        }                                                                      \
        __syncthreads();                                                       \
        _Pragma("unroll")                                                      \
        for (int ks = 0; ks < 2; ++ks) {                                       \
            uint32_t af[2][4];                                                 \
            _Pragma("unroll")                                                  \
            for (int mi = 0; mi < 2; ++mi)                                     \
                ldsm4(af[mi][0], af[mi][1], af[mi][2], af[mi][3],              \
                      smb + (uint32_t)GAH(buf, wm + mi * 16 + fr, ks * 16 + fc8) * 2); \
            _Pragma("unroll")                                                  \
            for (int nj = 0; nj < 4; ++nj) {                                   \
                uint32_t b0, b1, b2, b3;                                       \
                ldsm4(b0, b1, b2, b3,                                          \
                      smb + (uint32_t)GBH(buf, wn + nj * 16 + fr, ks * 16 + fc8) * 2); \
                MMA_F16(acc[0][2 * nj],     af[0][0], af[0][1], af[0][2], af[0][3], b0, b2); \
                MMA_F16(acc[0][2 * nj + 1], af[0][0], af[0][1], af[0][2], af[0][3], b1, b3); \
                MMA_F16(acc[1][2 * nj],     af[1][0], af[1][1], af[1][2], af[1][3], b0, b2); \
                MMA_F16(acc[1][2 * nj + 1], af[1][0], af[1][1], af[1][2], af[1][3], b1, b3); \
            }                                                                  \
        }                                                                      \
    }

// ================= QKV GEMM (fp16 MMA): xnh[8192,512] x WqkvTh =================
__global__ __launch_bounds__(256, 2) void qkv_mma_kernel() {
    __shared__ __half sm[20480];
    uint32_t smb = (uint32_t)__cvta_generic_to_shared(sm);
    int tid = threadIdx.x;
    int lane = tid & 31, wid = tid >> 5;
    int g = lane >> 2, tig = lane & 3;
    int fr = lane & 15, fc8 = (lane >> 4) * 8;
    int wm = (wid >> 1) * 32, wn = (wid & 1) * 64;
    int m0 = blockIdx.y * 128, n0 = blockIdx.x * 128;

    GEMM_MAIN(g_xnh, DD, g_wqkvTh, DD, DD);

    const float QSCALE = 0.125f * LOG2E;
#pragma unroll
    for (int ni = 0; ni < 8; ++ni) {
        int c = n0 + wn + ni * 8 + 2 * tig;
        int part = c >> 9, w = c & 511;
        int h = w >> 6, dd = w & 63;
#pragma unroll
        for (int mi = 0; mi < 2; ++mi) {
#pragma unroll
            for (int half = 0; half < 2; ++half) {
                int r = m0 + wm + mi * 16 + g + half * 8;
                int b = r >> 11, n = r & (NN - 1);
                size_t bh = (size_t)(b * HH + h);
                float v0 = acc[mi][ni][half * 2 + 0];
                float v1 = acc[mi][ni][half * 2 + 1];
                if (part == 0) {
                    *(__half2*)&g_qh[(bh * NN + n) * DH + dd] =
                        __floats2half2_rn(v0 * QSCALE, v1 * QSCALE);
                } else if (part == 1) {
                    *(__half2*)&g_kh[(bh * NN + n) * DH + dd] =
                        __floats2half2_rn(v0, v1);
                } else {
                    g_vTh[(bh * DH + dd) * NN + n]     = __float2half_rn(v0);
                    g_vTh[(bh * DH + dd + 1) * NN + n] = __float2half_rn(v1);
                }
            }
        }
    }
}

// ================= Out GEMM (fp16 MMA): attnh[8192,512] x WoutTh + bias =================
__global__ __launch_bounds__(256, 2) void out_mma_kernel(const float* __restrict__ bout,
                                                         float* __restrict__ out) {
    __shared__ __half sm[20480];
    uint32_t smb = (uint32_t)__cvta_generic_to_shared(sm);
    int tid = threadIdx.x;
    int lane = tid & 31, wid = tid >> 5;
    int g = lane >> 2, tig = lane & 3;
    int fr = lane & 15, fc8 = (lane >> 4) * 8;
    int wm = (wid >> 1) * 32, wn = (wid & 1) * 64;
    int m0 = blockIdx.y * 128, n0 = blockIdx.x * 128;

    GEMM_MAIN(g_attnh, HD, g_woutTh, HD, HD);

#pragma unroll
    for (int ni = 0; ni < 8; ++ni) {
        int c = n0 + wn + ni * 8 + 2 * tig;
        float2 bo = *(const float2*)&bout[c];
#pragma unroll
        for (int mi = 0; mi < 2; ++mi) {
#pragma unroll
            for (int half = 0; half < 2; ++half) {
                int r = m0 + wm + mi * 16 + g + half * 8;
                *(float2*)&out[(size_t)r * DD + c] =
                    make_float2(acc[mi][ni][half * 2 + 0] + bo.x,
                                acc[mi][ni][half * 2 + 1] + bo.y);
            }
        }
    }
}

// ================= Flash attention (R15 structure): fp16 MMA, reg-P, h2exp2, ones-MMA =================
// smem halves (stride 72): QS[128][72] @0, KS[2][64][72] @9216, VS[2][64][72] @18432
// (VS rows = d, cols = key).  Total 27648 halves = 54 KB.
#define HQS   0
#define HKS   9216
#define HVS   18432
#define HSTG  4608
#define FLASH_SMEM (27648 * 2)
#define NT_TILES (NN / 64)

__global__ __launch_bounds__(256, 2) void flash_mma_kernel() {
    extern __shared__ __half smh[];
    uint32_t smb = (uint32_t)__cvta_generic_to_shared(smh);

    int tid  = threadIdx.x;
    int lane = tid & 31, wid = tid >> 5;
    int g   = lane >> 2;
    int tig = lane & 3;
    int bh = blockIdx.y;
    int q0 = blockIdx.x * 128;
    const __half* Q  = g_qh  + (size_t)bh * NN * DH;
    const __half* K  = g_kh  + (size_t)bh * NN * DH;
    const __half* Vt = g_vTh + (size_t)bh * DH * NN;

    int hr = tid >> 3;            // 0..31
    int hc = (tid & 7) * 8;       // half col 0..56

#pragma unroll
    for (int i = 0; i < 4; ++i) {
        int r = hr + i * 32;
        cp16(smb + (HQS + r * 72 + hc) * 2, Q + (size_t)(q0 + r) * DH + hc);
    }
#pragma unroll
    for (int i = 0; i < 2; ++i) {
        int r = hr + i * 32;
        cp16(smb + (HKS + r * 72 + hc) * 2, K + (size_t)r * DH + hc);
        cp16(smb + (HVS + r * 72 + hc) * 2, Vt + (size_t)r * NN + hc);
    }
    CP_COMMIT();

    float oa[8][4] = {};
    float mi[2] = {-INFINITY, -INFINITY};
    float li[2] = {0.f, 0.f};
    const uint32_t ONES = 0x3C003C00u;   // half2(1.0, 1.0)

    const int m_row = wid * 16 + g;
    const int fr  = lane & 15;
    const int fc8 = (lane >> 4) * 8;
    const uint32_t qa_base = smb + ((uint32_t)(HQS + (wid * 16 + fr) * 72 + fc8) << 1);

    for (int t = 0; t < NT_TILES; ++t) {
        int cur = t & 1;
        int k0 = t * 64;

        __half2 bb[2][8];
        {
            const __half2* bp0 = (const __half2*)(g_biasH + (size_t)(q0 + m_row) * NN + k0) + tig;
            const __half2* bp1 = (const __half2*)(g_biasH + (size_t)(q0 + m_row + 8) * NN + k0) + tig;
#pragma unroll
            for (int nt = 0; nt < 8; ++nt) {
                bb[0][nt] = bp0[nt * 4];
                bb[1][nt] = bp1[nt * 4];
            }
        }

        if (t > 0) __syncthreads();
        if (t + 1 < NT_TILES) {
            int nxt = cur ^ 1;
#pragma unroll
            for (int i = 0; i < 2; ++i) {
                int r = hr + i * 32;
                cp16(smb + (HKS + nxt * HSTG + r * 72 + hc) * 2,
                     K + (size_t)(k0 + 64 + r) * DH + hc);
                cp16(smb + (HVS + nxt * HSTG + r * 72 + hc) * 2,
                     Vt + (size_t)r * NN + k0 + 64 + hc);
            }
            CP_COMMIT();
            CP_WAIT(1);
        } else {
            CP_WAIT(0);
        }
        __syncthreads();

        uint32_t kbase = smb + ((uint32_t)(HKS + cur * HSTG) << 1);
        uint32_t vbase = smb + ((uint32_t)(HVS + cur * HSTG) << 1);
        uint32_t ka[4], va[4];
#pragma unroll
        for (int j = 0; j < 4; ++j) {
            ka[j] = kbase + ((uint32_t)((j * 16 + fr) * 72 + fc8) << 1);
            va[j] = vbase + ((uint32_t)((j * 16 + fr) * 72 + fc8) << 1);
        }

        // ---- S accumulators initialized with fused bias ----
        float sa[8][4];
#pragma unroll
        for (int nt = 0; nt < 8; ++nt) {
            float2 b0 = __half22float2(bb[0][nt]);
            float2 b1 = __half22float2(bb[1][nt]);
            sa[nt][0] = b0.x; sa[nt][1] = b0.y;
            sa[nt][2] = b1.x; sa[nt][3] = b1.y;
        }

        // ---- S = bias + Q K^T (log2-domain) ----
        uint32_t qa = qa_base;
#pragma unroll
        for (int kc = 0; kc < 4; ++kc) {
            uint32_t a0, a1, a2, a3;
            ldsm4(a0, a1, a2, a3, qa);  qa += 32;
#pragma unroll
            for (int kt = 0; kt < 4; ++kt) {
                uint32_t b0, b1, b2, b3;
                ldsm4(b0, b1, b2, b3, ka[kt]);  ka[kt] += 32;
                MMA_F16(sa[2 * kt],     a0, a1, a2, a3, b0, b2);
                MMA_F16(sa[2 * kt + 1], a0, a1, a2, a3, b1, b3);
            }
        }

        // ---- online softmax: max (fp32) -> h2exp2 -> packed P fragments ----
        uint32_t ph[2][8];
        float fr2[2];
#pragma unroll
        for (int ri = 0; ri < 2; ++ri) {
            float mx = -INFINITY;
#pragma unroll
            for (int nt = 0; nt < 8; ++nt)
                mx = fmaxf(mx, fmaxf(sa[nt][ri * 2 + 0], sa[nt][ri * 2 + 1]));
            mx = fmaxf(mx, __shfl_xor_sync(0xffffffffu, mx, 1));
            mx = fmaxf(mx, __shfl_xor_sync(0xffffffffu, mx, 2));
            float mnew = fmaxf(mi[ri], mx);
            fr2[ri] = exp2f(mi[ri] - mnew);
#pragma unroll
            for (int nt = 0; nt < 8; ++nt) {
                __half2 tt = __floats2half2_rn(sa[nt][ri * 2 + 0] - mnew,
                                               sa[nt][ri * 2 + 1] - mnew);
                __half2 e = h2exp2(tt);
                ph[ri][nt] = *(uint32_t*)&e;
            }
            mi[ri] = mnew;
#pragma unroll
            for (int nt = 0; nt < 8; ++nt) {
                oa[nt][ri * 2 + 0] *= fr2[ri];
                oa[nt][ri * 2 + 1] *= fr2[ri];
            }
        }

        // ---- O += P V, and row-sums via ones-MMA ----
        float ls[4] = {};
#pragma unroll
        for (int kc = 0; kc < 4; ++kc) {
            uint32_t a0 = ph[0][2 * kc];
            uint32_t a1 = ph[1][2 * kc];
            uint32_t a2 = ph[0][2 * kc + 1];
            uint32_t a3 = ph[1][2 * kc + 1];
            MMA_F16(ls, a0, a1, a2, a3, ONES, ONES);
#pragma unroll
            for (int dt = 0; dt < 4; ++dt) {
                uint32_t b0, b1, b2, b3;
                ldsm4(b0, b1, b2, b3, va[dt]);  va[dt] += 32;
                MMA_F16(oa[2 * dt],     a0, a1, a2, a3, b0, b2);
                MMA_F16(oa[2 * dt + 1], a0, a1, a2, a3, b1, b3);
            }
        }
        li[0] = li[0] * fr2[0] + ls[0];
        li[1] = li[1] * fr2[1] + ls[2];
    }

    // ---- finalize: fp16 attn [B, N, H*d] ----
    int b = bh >> 3, h = bh & 7;
    float inv0 = 1.0f / li[0], inv1 = 1.0f / li[1];
#pragma unroll
    for (int nt = 0; nt < 8; ++nt) {
        int col = h * DH + nt * 8 + 2 * tig;
        int r0 = q0 + m_row;
        *(__half2*)&g_attnh[((size_t)(b * NN + r0)) * HD + col] =
            __floats2half2_rn(oa[nt][0] * inv0, oa[nt][1] * inv0);
        *(__half2*)&g_attnh[((size_t)(b * NN + r0 + 8)) * HD + col] =
            __floats2half2_rn(oa[nt][2] * inv1, oa[nt][3] * inv1);
    }
}

extern "C" void kernel_launch(void* const* d_in, const int* in_sizes, int n_in,
                              void* d_out, int out_size) {
    const float* x     = (const float*)d_in[0];
    const float* gamma = (const float*)d_in[1];
    const float* beta  = (const float*)d_in[2];
    const float* Wqkv  = (const float*)d_in[3];
    const float* Wout  = (const float*)d_in[4];
    const float* bout  = (const float*)d_in[5];
    const float* rel   = (const float*)d_in[6];
    const int*   tmask = (const int*)d_in[7];
    float* out = (float*)d_out;

    prep_kernel<<<6144, 256>>>(x, gamma, beta, Wqkv, Wout, rel, tmask);
    qkv_mma_kernel<<<dim3(QKVC / 128, (BB * NN) / 128), 256>>>();

    cudaFuncSetAttribute(flash_mma_kernel, cudaFuncAttributeMaxDynamicSharedMemorySize, FLASH_SMEM);
    flash_mma_kernel<<<dim3(NN / 128, BB * HH), 256, FLASH_SMEM>>>();

    out_mma_kernel<<<dim3(DD / 128, (BB * NN) / 128), 256>>>(bout, out);
}